// round 7
// baseline (speedup 1.0000x reference)
#include <cuda_runtime.h>
#include <math.h>

#define NBATCH 4
#define NATOM  512
#define NSYM   4
#define NLAB   16
#define C1     32
#define C2     64
#define NTHR   256
#define GA     4          // atoms per CTA
#define MAXNB  96
#define C1P    68         // padded centres1 / LmT row (floats)
#define LUTN   513
#define LUTS   516        // padded LUT row stride
#define SQK    1.2011224087864498f   // sqrt(log2(e))

__device__ float g_lut[NLAB * LUTS];   // rs(fc,lab) * sigma1 * SQK

__constant__ int   c_pf[16] = {0,0,0,0,1,1,1,2,2,3, 0,0,0,0,0,0};
__constant__ int   c_ph[16] = {0,1,2,3,1,2,3,2,3,3, 0,0,0,0,0,0};
__constant__ float c_pw[16] = {1,2,2,2,1,2,2,1,2,1, 0,0,0,0,0,0};

__device__ __forceinline__ float ex2(float x) {
    float r; asm("ex2.approx.ftz.f32 %0, %1;" : "=f"(r) : "f"(x)); return r;
}

// ---- LUT precompute: lut[lab][q] = w0*sum_k exp(-((q/512 - c0_k)*s0)^2) * s1 * SQK
__global__ void lut_kernel(const float* __restrict__ nuww0,
                           const float* __restrict__ sigmas0,
                           const float* __restrict__ centres0,
                           const float* __restrict__ sigmas1)
{
    const int idx = blockIdx.x * blockDim.x + threadIdx.x;
    const int sub = idx & 3;
    const int pq0 = idx >> 2;
    const int pq  = (pq0 < NLAB * LUTN) ? pq0 : (NLAB * LUTN - 1);
    const int lab = pq / LUTN;
    const int q   = pq - lab * LUTN;
    const float fc = (float)q * (1.0f / 512.0f);
    const float s0 = sigmas0[lab];
    float sum = 0.0f;
    #pragma unroll
    for (int k = sub; k < C1; k += 4) {
        const float a = (fc - centres0[lab * C1 + k]) * s0;
        sum += __expf(-a * a);
    }
    sum += __shfl_xor_sync(0xffffffffu, sum, 1);
    sum += __shfl_xor_sync(0xffffffffu, sum, 2);
    if (sub == 0 && pq0 < NLAB * LUTN)
        g_lut[lab * LUTS + q] = nuww0[lab] * sum * sigmas1[lab] * SQK;
}

__global__ __launch_bounds__(NTHR)
void descriptor_kernel(const int*   __restrict__ numbers,
                       const float* __restrict__ coords,
                       const float* __restrict__ nuww1,
                       const float* __restrict__ sigmas1,
                       const float* __restrict__ centres1,
                       float*       __restrict__ out)
{
    __shared__ float4 s_pos[NATOM];                  // 8 KB
    __shared__ float  s_sc1[NLAB * C1P];             // 4.25 KB (c1*s1*SQK, padded)
    __shared__ float  s_w1[NLAB];
    __shared__ float4 nb_f4[GA][MAXNB];              // 6 KB  (w1*fc, w1*gx, w1*gy, w1*gz)
    __shared__ float2 nb_meta[GA][MAXNB];            // 3 KB  (rs*s1*SQK, row offset)
    __shared__ float  LmT [GA][4][C1P];              // 4.25 KB
    __shared__ float  LmTs[GA][4][C1P];              // 4.25 KB (rf-scaled copy)
    __shared__ int    s_wcnt[GA][2];

    const int tid  = threadIdx.x;
    const int bidx = blockIdx.x;
    const int b    = bidx >> 7;                      // 128 CTAs per batch
    const int li0  = (bidx & 127) * GA;
    const int lane = tid & 31;
    const int warp = tid >> 5;
    const int g    = tid >> 6;                       // atom served (0..3)
    const int t64  = tid & 63;

    // ---- cooperative loads + table pre-scaling ----
    {
        const float* cb  = coords  + (size_t)b * NATOM * 3;
        const int*   nbp = numbers + (size_t)b * NATOM;
        for (int t = tid; t < NATOM; t += NTHR)
            s_pos[t] = make_float4(cb[t * 3 + 0], cb[t * 3 + 1], cb[t * 3 + 2],
                                   __int_as_float(nbp[t]));
        for (int t = tid; t < NLAB * C2; t += NTHR) {
            const int lab = t >> 6, c = t & 63;
            s_sc1[lab * C1P + c] = centres1[t] * sigmas1[lab] * SQK;
        }
        if (tid < NLAB) s_w1[tid] = nuww1[tid];
    }
    __syncthreads();

    // ---- Phase 1a: ballot compaction + inline first-RConv via LUT ----
    {
        const int ww = (tid >> 5) & 1;
        const int il = li0 + g;
        const float4 ci = s_pos[il];
        const float xi = ci.x, yi = ci.y, zi = ci.z;

        unsigned mk[8];
        int cnt = 0;
        #pragma unroll
        for (int c = 0; c < 8; c++) {
            const int j = ww * 256 + c * 32 + lane;
            const float4 p = s_pos[j];
            const float dx = p.x - xi, dy = p.y - yi, dz = p.z - zi;
            const float d2 = dx * dx + dy * dy + dz * dz;
            const bool f = (j != il) && (d2 <= 36.0f);
            mk[c] = __ballot_sync(0xffffffffu, f);
            cnt += __popc(mk[c]);
        }
        if (lane == 0) s_wcnt[g][ww] = cnt;
        __syncthreads();

        int base = (ww == 1) ? s_wcnt[g][0] : 0;
        const unsigned ltmask = (1u << lane) - 1u;
        const int zbase = __float_as_int(ci.w) * NSYM;
        #pragma unroll
        for (int c = 0; c < 8; c++) {
            if ((mk[c] >> lane) & 1u) {
                const int pos = base + __popc(mk[c] & ltmask);
                if (pos < MAXNB) {
                    const int j = ww * 256 + c * 32 + lane;
                    const float4 p = s_pos[j];
                    const float dx = p.x - xi, dy = p.y - yi, dz = p.z - zi;
                    const float d2 = dx * dx + dy * dy + dz * dz;
                    const float rinv = (d2 > 0.0f) ? rsqrtf(d2) : 0.0f;
                    const float d    = d2 * rinv;
                    const float fcv  = 0.5f * __cosf(d * 0.52359877559829887f) + 0.5f;
                    const int   lab  = zbase + __float_as_int(p.w);
                    // first RConv via LUT (513 samples, linear interp)
                    const float u  = fcv * 512.0f;
                    int i0 = (int)u; i0 = (i0 < 512) ? i0 : 511;
                    const float fr = u - (float)i0;
                    const float v0 = __ldg(&g_lut[lab * LUTS + i0]);
                    const float v1 = __ldg(&g_lut[lab * LUTS + i0 + 1]);
                    const float mx = fmaf(fr, v1 - v0, v0);
                    const float w1 = s_w1[lab];
                    const float gg = rinv * fcv * w1;
                    nb_f4[g][pos]   = make_float4(fcv * w1, dx * gg, dy * gg, dz * gg);
                    nb_meta[g][pos] = make_float2(mx, __int_as_float(lab * C1P));
                }
            }
            base += __popc(mk[c]);
        }
    }
    __syncthreads();

    const int nnb = min(s_wcnt[g][0] + s_wcnt[g][1], MAXNB);

    // ---- Phase 2: second RConv + Lm. 4 c2 x 4 neighbor-slices per thread ----
    {
        const int lw    = t64 >> 5;
        const int l5    = t64 & 31;
        const int grp   = l5 >> 2;
        const int slice = l5 & 3;
        const int c2b   = (lw * 8 + grp) * 4;

        float acc[4][4];
        #pragma unroll
        for (int a = 0; a < 4; a++)
            #pragma unroll
            for (int f = 0; f < 4; f++) acc[a][f] = 0.0f;

        for (int k = slice; k < nnb; k += 4) {
            const float2 m = nb_meta[g][k];
            const float4 cc = *reinterpret_cast<const float4*>(
                &s_sc1[__float_as_int(m.y) + c2b]);
            const float t0 = m.x - cc.x, t1 = m.x - cc.y;
            const float t2 = m.x - cc.z, t3 = m.x - cc.w;
            const float p0 = ex2(-t0 * t0), p1 = ex2(-t1 * t1);
            const float p2 = ex2(-t2 * t2), p3 = ex2(-t3 * t3);
            const float4 f = nb_f4[g][k];
            acc[0][0] = fmaf(p0, f.x, acc[0][0]); acc[0][1] = fmaf(p0, f.y, acc[0][1]);
            acc[0][2] = fmaf(p0, f.z, acc[0][2]); acc[0][3] = fmaf(p0, f.w, acc[0][3]);
            acc[1][0] = fmaf(p1, f.x, acc[1][0]); acc[1][1] = fmaf(p1, f.y, acc[1][1]);
            acc[1][2] = fmaf(p1, f.z, acc[1][2]); acc[1][3] = fmaf(p1, f.w, acc[1][3]);
            acc[2][0] = fmaf(p2, f.x, acc[2][0]); acc[2][1] = fmaf(p2, f.y, acc[2][1]);
            acc[2][2] = fmaf(p2, f.z, acc[2][2]); acc[2][3] = fmaf(p2, f.w, acc[2][3]);
            acc[3][0] = fmaf(p3, f.x, acc[3][0]); acc[3][1] = fmaf(p3, f.y, acc[3][1]);
            acc[3][2] = fmaf(p3, f.z, acc[3][2]); acc[3][3] = fmaf(p3, f.w, acc[3][3]);
        }
        #pragma unroll
        for (int a = 0; a < 4; a++)
            #pragma unroll
            for (int f = 0; f < 4; f++) {
                float v = acc[a][f];
                v += __shfl_xor_sync(0xffffffffu, v, 1);
                v += __shfl_xor_sync(0xffffffffu, v, 2);
                acc[a][f] = v;
            }
        if (slice == 0) {
            #pragma unroll
            for (int f = 0; f < 4; f++)
                *reinterpret_cast<float4*>(&LmT[g][f][c2b]) =
                    make_float4(acc[0][f], acc[1][f], acc[2][f], acc[3][f]);
        }
    }
    __syncthreads();

    // ---- Warp-per-atom epilogue: Gram -> rf -> scaled copy, all in-warp ----
    if (warp < GA) {
        const int g2   = warp;
        const int p    = lane >> 1;                  // 0..15
        const int part = lane & 1;
        const int pc   = (p < 10) ? p : 9;
        const float4* rf4 = reinterpret_cast<const float4*>(&LmT[g2][c_pf[pc]][part * 32]);
        const float4* rh4 = reinterpret_cast<const float4*>(&LmT[g2][c_ph[pc]][part * 32]);
        float s = 0.0f;
        #pragma unroll
        for (int q = 0; q < 8; q++) {
            const float4 x = rf4[q], y = rh4[q];
            s = fmaf(x.x, y.x, s); s = fmaf(x.y, y.y, s);
            s = fmaf(x.z, y.z, s); s = fmaf(x.w, y.w, s);
        }
        s += __shfl_xor_sync(0xffffffffu, s, 1);     // combine the two halves -> G_pc
        const float wq = (p < 10 && part == 0) ? c_pw[pc] : 0.0f;
        float tot = wq * s * s;
        tot += __shfl_xor_sync(0xffffffffu, tot, 1);
        tot += __shfl_xor_sync(0xffffffffu, tot, 2);
        tot += __shfl_xor_sync(0xffffffffu, tot, 4);
        tot += __shfl_xor_sync(0xffffffffu, tot, 8);
        tot += __shfl_xor_sync(0xffffffffu, tot, 16);
        const float rfv = rsqrtf(tot);
        // rf-scaled copy: each lane scales 8 consecutive entries
        const int base = lane * 8;
        const int ffb = base >> 6, ccb = base & 63;
        float4 v0 = *reinterpret_cast<const float4*>(&LmT[g2][ffb][ccb]);
        float4 v1 = *reinterpret_cast<const float4*>(&LmT[g2][ffb][ccb + 4]);
        v0.x *= rfv; v0.y *= rfv; v0.z *= rfv; v0.w *= rfv;
        v1.x *= rfv; v1.y *= rfv; v1.z *= rfv; v1.w *= rfv;
        *reinterpret_cast<float4*>(&LmTs[g2][ffb][ccb])     = v0;
        *reinterpret_cast<float4*>(&LmTs[g2][ffb][ccb + 4]) = v1;
    }
    __syncthreads();

    // ---- Phase 3: R = Lm (rf*Lm)^T; barrier-free stores ----
    const int dd0  = (tid * 4) & 63;
    const int crow = tid >> 4;                       // 0..15
    #pragma unroll
    for (int g2 = 0; g2 < GA; g2++) {
        const float4 b0 = *reinterpret_cast<const float4*>(&LmTs[g2][0][dd0]);
        const float4 b1 = *reinterpret_cast<const float4*>(&LmTs[g2][1][dd0]);
        const float4 b2 = *reinterpret_cast<const float4*>(&LmTs[g2][2][dd0]);
        const float4 b3 = *reinterpret_cast<const float4*>(&LmTs[g2][3][dd0]);
        float* ob = out + ((size_t)(bidx * GA + g2) << 12);
        #pragma unroll
        for (int grp = 0; grp < 4; grp++) {
            const int c = grp * 16 + crow;
            const float a0 = LmT[g2][0][c], a1 = LmT[g2][1][c];
            const float a2 = LmT[g2][2][c], a3 = LmT[g2][3][c];
            float4 st;
            st.x = fmaf(a3, b3.x, fmaf(a2, b2.x, fmaf(a1, b1.x, a0 * b0.x)));
            st.y = fmaf(a3, b3.y, fmaf(a2, b2.y, fmaf(a1, b1.y, a0 * b0.y)));
            st.z = fmaf(a3, b3.z, fmaf(a2, b2.z, fmaf(a1, b1.z, a0 * b0.z)));
            st.w = fmaf(a3, b3.w, fmaf(a2, b2.w, fmaf(a1, b1.w, a0 * b0.w)));
            *reinterpret_cast<float4*>(ob + (grp << 10) + tid * 4) = st;
        }
    }
}

extern "C" void kernel_launch(void* const* d_in, const int* in_sizes, int n_in,
                              void* d_out, int out_size)
{
    // metadata order: boxs, numbers, coords, nuww0, sigmas0, centres0, nuww1, sigmas1, centres1
    const int*   numbers  = (const int*)  d_in[1];
    const float* coords   = (const float*)d_in[2];
    const float* nuww0    = (const float*)d_in[3];
    const float* sigmas0  = (const float*)d_in[4];
    const float* centres0 = (const float*)d_in[5];
    const float* nuww1    = (const float*)d_in[6];
    const float* sigmas1  = (const float*)d_in[7];
    const float* centres1 = (const float*)d_in[8];
    float* out = (float*)d_out;

    const int lut_threads = NLAB * LUTN * 4;
    lut_kernel<<<(lut_threads + 255) / 256, 256>>>(nuww0, sigmas0, centres0, sigmas1);
    descriptor_kernel<<<(NBATCH * NATOM) / GA, NTHR>>>(
        numbers, coords, nuww1, sigmas1, centres1, out);
}

// round 8
// speedup vs baseline: 1.0883x; 1.0883x over previous
#include <cuda_runtime.h>
#include <math.h>

#define NBATCH 4
#define NATOM  512
#define NSYM   4
#define NLAB   16
#define C1     32
#define C2     64
#define NTHR   128
#define GA     2          // atoms per CTA
#define MAXNB  96
#define C0P    36         // padded centres0 row (floats)
#define C1P    68         // padded centres1 / LmT row (floats)
#define SQK    1.2011224087864498f   // sqrt(log2(e))

__constant__ int   c_pf[16] = {0,0,0,0,1,1,1,2,2,3, 0,0,0,0,0,0};
__constant__ int   c_ph[16] = {0,1,2,3,1,2,3,2,3,3, 0,0,0,0,0,0};
__constant__ float c_pw[16] = {1,2,2,2,1,2,2,1,2,1, 0,0,0,0,0,0};

__device__ __forceinline__ float ex2(float x) {
    float r; asm("ex2.approx.ftz.f32 %0, %1;" : "=f"(r) : "f"(x)); return r;
}

__global__ __launch_bounds__(NTHR)
void descriptor_kernel(const int*   __restrict__ numbers,
                       const float* __restrict__ coords,
                       const float* __restrict__ nuww0,
                       const float* __restrict__ sigmas0,
                       const float* __restrict__ centres0,
                       const float* __restrict__ nuww1,
                       const float* __restrict__ sigmas1,
                       const float* __restrict__ centres1,
                       float*       __restrict__ out)
{
    __shared__ float4 s_pos[NATOM];                  // 8 KB
    __shared__ float  s_c0s[NLAB * C0P];             // 2.25 KB (c0*s0*SQK, padded)
    __shared__ float  s_sc1[NLAB * C1P];             // 4.25 KB (c1*s1*SQK, padded)
    __shared__ float  s_w0[NLAB], s_s0f[NLAB], s_w1[NLAB], s_s1f[NLAB];
    __shared__ float4 nb_f4[GA][MAXNB];              // 3 KB
    __shared__ float2 nb_meta[GA][MAXNB];            // 1.5 KB (rs*s1*SQK, row offset)
    __shared__ int    s_lab[GA][MAXNB];              // 0.75 KB
    __shared__ float  LmT [GA][4][C1P];              // 2.13 KB
    __shared__ float  LmTs[GA][4][C1P];              // 2.13 KB (rf-scaled copy)
    __shared__ int    s_wcnt[GA][2];

    const int tid  = threadIdx.x;
    const int bidx = blockIdx.x;
    const int b    = bidx >> 8;                      // 256 CTAs per batch
    const int li0  = (bidx & 255) * GA;
    const int lane = tid & 31;
    const int warp = tid >> 5;
    const int g    = tid >> 6;                       // atom served (0/1)
    const int t64  = tid & 63;

    // ---- cooperative loads + folded table pre-scaling ----
    {
        const float* cb  = coords  + (size_t)b * NATOM * 3;
        const int*   nbp = numbers + (size_t)b * NATOM;
        for (int t = tid; t < NATOM; t += NTHR)
            s_pos[t] = make_float4(cb[t * 3 + 0], cb[t * 3 + 1], cb[t * 3 + 2],
                                   __int_as_float(nbp[t]));
        for (int t = tid; t < NLAB * C1; t += NTHR) {
            const int lab = t >> 5, c = t & 31;
            s_c0s[lab * C0P + c] = centres0[t] * sigmas0[lab] * SQK;
        }
        for (int t = tid; t < NLAB * C2; t += NTHR) {
            const int lab = t >> 6, c = t & 63;
            s_sc1[lab * C1P + c] = centres1[t] * sigmas1[lab] * SQK;
        }
        if (tid < NLAB) {
            s_w0[tid]  = nuww0[tid];  s_s0f[tid] = sigmas0[tid] * SQK;
            s_w1[tid]  = nuww1[tid];  s_s1f[tid] = sigmas1[tid] * SQK;
        }
    }
    __syncthreads();

    // ---- Phase 1a: ballot compaction (2 warps/atom, 8 chunks each) ----
    {
        const int ww = (tid >> 5) & 1;
        const int il = li0 + g;
        const float4 ci = s_pos[il];
        const float xi = ci.x, yi = ci.y, zi = ci.z;

        unsigned mk[8];
        int cnt = 0;
        #pragma unroll
        for (int c = 0; c < 8; c++) {
            const int j = ww * 256 + c * 32 + lane;
            const float4 p = s_pos[j];
            const float dx = p.x - xi, dy = p.y - yi, dz = p.z - zi;
            const float d2 = dx * dx + dy * dy + dz * dz;
            const bool f = (j != il) && (d2 <= 36.0f);
            mk[c] = __ballot_sync(0xffffffffu, f);
            cnt += __popc(mk[c]);
        }
        if (lane == 0) s_wcnt[g][ww] = cnt;
        __syncthreads();

        int base = (ww == 1) ? s_wcnt[g][0] : 0;
        const unsigned ltmask = (1u << lane) - 1u;
        const int zbase = __float_as_int(ci.w) * NSYM;
        #pragma unroll
        for (int c = 0; c < 8; c++) {
            if ((mk[c] >> lane) & 1u) {
                const int pos = base + __popc(mk[c] & ltmask);
                if (pos < MAXNB) {
                    const int j = ww * 256 + c * 32 + lane;
                    const float4 p = s_pos[j];
                    const float dx = p.x - xi, dy = p.y - yi, dz = p.z - zi;
                    const float d2 = dx * dx + dy * dy + dz * dz;
                    const float rinv = (d2 > 0.0f) ? rsqrtf(d2) : 0.0f;
                    const float d    = d2 * rinv;
                    const float fc   = 0.5f * __cosf(d * 0.52359877559829887f) + 0.5f;
                    const float gg   = rinv * fc;
                    nb_f4[g][pos] = make_float4(fc, dx * gg, dy * gg, dz * gg);
                    s_lab[g][pos] = zbase + __float_as_int(p.w);
                }
            }
            base += __popc(mk[c]);
        }
    }
    __syncthreads();

    const int nnb = min(s_wcnt[g][0] + s_wcnt[g][1], MAXNB);

    // ---- Phase 1b: first RConv (8 thr/pair, 8 pairs/sweep/atom) ----
    {
        const int sub  = t64 & 7;
        const int slot = t64 >> 3;                   // 0..7
        const int nIter = (nnb + 7) >> 3;            // warp-uniform (same g per warp)
        for (int it = 0; it < nIter; it++) {
            const int p  = slot + (it << 3);
            const int pc = (p < nnb) ? p : (nnb - 1);
            const int   lab = s_lab[g][pc];
            const float fc  = nb_f4[g][pc].x;
            const float fcs = fc * s_s0f[lab];
            const float4 c4 = *reinterpret_cast<const float4*>(&s_c0s[lab * C0P + sub * 4]);
            const float a0 = fcs - c4.x, a1 = fcs - c4.y, a2 = fcs - c4.z, a3 = fcs - c4.w;
            float sum = ex2(-a0 * a0) + ex2(-a1 * a1) + ex2(-a2 * a2) + ex2(-a3 * a3);
            sum += __shfl_xor_sync(0xffffffffu, sum, 1);
            sum += __shfl_xor_sync(0xffffffffu, sum, 2);
            sum += __shfl_xor_sync(0xffffffffu, sum, 4);
            if (sub == 0 && p < nnb) {
                const float rs = s_w0[lab] * sum;
                const float w1 = s_w1[lab];
                nb_meta[g][p] = make_float2(rs * s_s1f[lab],
                                            __int_as_float(lab * C1P));
                float4 f = nb_f4[g][p];
                f.x *= w1; f.y *= w1; f.z *= w1; f.w *= w1;
                nb_f4[g][p] = f;
            }
        }
    }
    __syncthreads();

    // ---- Phase 2: second RConv + Lm. 4 c2 x 4 neighbor-slices per thread ----
    {
        const int lw    = t64 >> 5;
        const int l5    = t64 & 31;
        const int grp   = l5 >> 2;
        const int slice = l5 & 3;
        const int c2b   = (lw * 8 + grp) * 4;

        float acc[4][4];
        #pragma unroll
        for (int a = 0; a < 4; a++)
            #pragma unroll
            for (int f = 0; f < 4; f++) acc[a][f] = 0.0f;

        for (int k = slice; k < nnb; k += 4) {
            const float2 m = nb_meta[g][k];
            const float4 cc = *reinterpret_cast<const float4*>(
                &s_sc1[__float_as_int(m.y) + c2b]);
            const float t0 = m.x - cc.x, t1 = m.x - cc.y;
            const float t2 = m.x - cc.z, t3 = m.x - cc.w;
            const float p0 = ex2(-t0 * t0), p1 = ex2(-t1 * t1);
            const float p2 = ex2(-t2 * t2), p3 = ex2(-t3 * t3);
            const float4 f = nb_f4[g][k];
            acc[0][0] = fmaf(p0, f.x, acc[0][0]); acc[0][1] = fmaf(p0, f.y, acc[0][1]);
            acc[0][2] = fmaf(p0, f.z, acc[0][2]); acc[0][3] = fmaf(p0, f.w, acc[0][3]);
            acc[1][0] = fmaf(p1, f.x, acc[1][0]); acc[1][1] = fmaf(p1, f.y, acc[1][1]);
            acc[1][2] = fmaf(p1, f.z, acc[1][2]); acc[1][3] = fmaf(p1, f.w, acc[1][3]);
            acc[2][0] = fmaf(p2, f.x, acc[2][0]); acc[2][1] = fmaf(p2, f.y, acc[2][1]);
            acc[2][2] = fmaf(p2, f.z, acc[2][2]); acc[2][3] = fmaf(p2, f.w, acc[2][3]);
            acc[3][0] = fmaf(p3, f.x, acc[3][0]); acc[3][1] = fmaf(p3, f.y, acc[3][1]);
            acc[3][2] = fmaf(p3, f.z, acc[3][2]); acc[3][3] = fmaf(p3, f.w, acc[3][3]);
        }
        #pragma unroll
        for (int a = 0; a < 4; a++)
            #pragma unroll
            for (int f = 0; f < 4; f++) {
                float v = acc[a][f];
                v += __shfl_xor_sync(0xffffffffu, v, 1);
                v += __shfl_xor_sync(0xffffffffu, v, 2);
                acc[a][f] = v;
            }
        if (slice == 0) {
            #pragma unroll
            for (int f = 0; f < 4; f++)
                *reinterpret_cast<float4*>(&LmT[g][f][c2b]) =
                    make_float4(acc[0][f], acc[1][f], acc[2][f], acc[3][f]);
        }
    }
    __syncthreads();

    // ---- Warp-per-atom epilogue: Gram -> rf -> scaled copy, all in-warp ----
    if (warp < GA) {
        const int g2   = warp;
        const int p    = lane >> 1;                  // 0..15
        const int part = lane & 1;
        const int pc   = (p < 10) ? p : 9;
        const float4* rf4 = reinterpret_cast<const float4*>(&LmT[g2][c_pf[pc]][part * 32]);
        const float4* rh4 = reinterpret_cast<const float4*>(&LmT[g2][c_ph[pc]][part * 32]);
        float s = 0.0f;
        #pragma unroll
        for (int q = 0; q < 8; q++) {
            const float4 x = rf4[q], y = rh4[q];
            s = fmaf(x.x, y.x, s); s = fmaf(x.y, y.y, s);
            s = fmaf(x.z, y.z, s); s = fmaf(x.w, y.w, s);
        }
        s += __shfl_xor_sync(0xffffffffu, s, 1);     // combine halves -> G_pc
        const float wq = (p < 10 && part == 0) ? c_pw[pc] : 0.0f;
        float tot = wq * s * s;
        tot += __shfl_xor_sync(0xffffffffu, tot, 1);
        tot += __shfl_xor_sync(0xffffffffu, tot, 2);
        tot += __shfl_xor_sync(0xffffffffu, tot, 4);
        tot += __shfl_xor_sync(0xffffffffu, tot, 8);
        tot += __shfl_xor_sync(0xffffffffu, tot, 16);
        const float rfv = rsqrtf(tot);
        const int base = lane * 8;
        const int ffb = base >> 6, ccb = base & 63;
        float4 v0 = *reinterpret_cast<const float4*>(&LmT[g2][ffb][ccb]);
        float4 v1 = *reinterpret_cast<const float4*>(&LmT[g2][ffb][ccb + 4]);
        v0.x *= rfv; v0.y *= rfv; v0.z *= rfv; v0.w *= rfv;
        v1.x *= rfv; v1.y *= rfv; v1.z *= rfv; v1.w *= rfv;
        *reinterpret_cast<float4*>(&LmTs[g2][ffb][ccb])     = v0;
        *reinterpret_cast<float4*>(&LmTs[g2][ffb][ccb + 4]) = v1;
    }
    __syncthreads();

    // ---- Phase 3: R = Lm (rf*Lm)^T; 8 float4 stores per thread per atom ----
    const int dd0  = (tid * 4) & 63;
    const int crw  = tid >> 4;                       // 0..7
    #pragma unroll
    for (int g2 = 0; g2 < GA; g2++) {
        const float4 b0 = *reinterpret_cast<const float4*>(&LmTs[g2][0][dd0]);
        const float4 b1 = *reinterpret_cast<const float4*>(&LmTs[g2][1][dd0]);
        const float4 b2 = *reinterpret_cast<const float4*>(&LmTs[g2][2][dd0]);
        const float4 b3 = *reinterpret_cast<const float4*>(&LmTs[g2][3][dd0]);
        float* ob = out + ((size_t)(bidx * GA + g2) << 12);
        #pragma unroll
        for (int grp = 0; grp < 8; grp++) {
            const int c = grp * 8 + crw;
            const float a0 = LmT[g2][0][c], a1 = LmT[g2][1][c];
            const float a2 = LmT[g2][2][c], a3 = LmT[g2][3][c];
            float4 st;
            st.x = fmaf(a3, b3.x, fmaf(a2, b2.x, fmaf(a1, b1.x, a0 * b0.x)));
            st.y = fmaf(a3, b3.y, fmaf(a2, b2.y, fmaf(a1, b1.y, a0 * b0.y)));
            st.z = fmaf(a3, b3.z, fmaf(a2, b2.z, fmaf(a1, b1.z, a0 * b0.z)));
            st.w = fmaf(a3, b3.w, fmaf(a2, b2.w, fmaf(a1, b1.w, a0 * b0.w)));
            *reinterpret_cast<float4*>(ob + (grp << 9) + tid * 4) = st;
        }
    }
}

extern "C" void kernel_launch(void* const* d_in, const int* in_sizes, int n_in,
                              void* d_out, int out_size)
{
    // metadata order: boxs, numbers, coords, nuww0, sigmas0, centres0, nuww1, sigmas1, centres1
    const int*   numbers  = (const int*)  d_in[1];
    const float* coords   = (const float*)d_in[2];
    const float* nuww0    = (const float*)d_in[3];
    const float* sigmas0  = (const float*)d_in[4];
    const float* centres0 = (const float*)d_in[5];
    const float* nuww1    = (const float*)d_in[6];
    const float* sigmas1  = (const float*)d_in[7];
    const float* centres1 = (const float*)d_in[8];
    float* out = (float*)d_out;

    descriptor_kernel<<<(NBATCH * NATOM) / GA, NTHR>>>(
        numbers, coords, nuww0, sigmas0, centres0, nuww1, sigmas1, centres1, out);
}